// round 1
// baseline (speedup 1.0000x reference)
#include <cuda_runtime.h>

#define HH 512
#define WW 512
#define RPB 32            // rows per block
#define TPB 128           // threads per block: 128 * 4 cols = 512 = WW
#define EPS 1e-6f

// scratch for per-block partial sums (no cudaMalloc allowed)
__device__ float g_partials[8192];

__device__ __forceinline__ float4 ld4(const float* __restrict__ p) {
    return *reinterpret_cast<const float4*>(p);
}

__global__ __launch_bounds__(TPB)
void grad_loss_kernel(const float* __restrict__ in, const float* __restrict__ tg) {
    const int t  = threadIdx.x;
    const int w0 = t * 4;
    const int bands_per_plane = HH / RPB;
    const int plane = blockIdx.x / bands_per_plane;
    const int band  = blockIdx.x % bands_per_plane;
    const int r0 = band * RPB;

    const float* __restrict__ bi = in + (size_t)plane * HH * WW;
    const float* __restrict__ bt = tg + (size_t)plane * HH * WW;

    float4 ui, ci, di, ut, ct, dt;
    const float4 z4 = make_float4(0.f, 0.f, 0.f, 0.f);

    if (r0 > 0) {
        ui = ld4(bi + (size_t)(r0 - 1) * WW + w0);
        ut = ld4(bt + (size_t)(r0 - 1) * WW + w0);
    } else {
        ui = z4; ut = z4;
    }
    ci = ld4(bi + (size_t)r0 * WW + w0);
    ct = ld4(bt + (size_t)r0 * WW + w0);

    float sum = 0.f;

    #pragma unroll 4
    for (int r = r0; r < r0 + RPB; ++r) {
        if (r + 1 < HH) {
            di = ld4(bi + (size_t)(r + 1) * WW + w0);
            dt = ld4(bt + (size_t)(r + 1) * WW + w0);
        } else {
            di = z4; dt = z4;
        }
        // horizontal neighbors at the float4 boundaries (L1 hits: same lines as
        // neighboring threads' vector loads)
        const float lci = (w0 > 0)        ? bi[(size_t)r * WW + w0 - 1] : 0.f;
        const float rci = (w0 + 4 < WW)   ? bi[(size_t)r * WW + w0 + 4] : 0.f;
        const float lct = (w0 > 0)        ? bt[(size_t)r * WW + w0 - 1] : 0.f;
        const float rct = (w0 + 4 < WW)   ? bt[(size_t)r * WW + w0 + 4] : 0.f;

        float gv, gh, a, b;

        // pixel j=0
        gv = di.x - ui.x; gh = ci.y - lci;
        a  = sqrtf(fmaf(gv, gv, fmaf(gh, gh, EPS)));
        gv = dt.x - ut.x; gh = ct.y - lct;
        b  = sqrtf(fmaf(gv, gv, fmaf(gh, gh, EPS)));
        sum += fabsf(a - b);

        // pixel j=1
        gv = di.y - ui.y; gh = ci.z - ci.x;
        a  = sqrtf(fmaf(gv, gv, fmaf(gh, gh, EPS)));
        gv = dt.y - ut.y; gh = ct.z - ct.x;
        b  = sqrtf(fmaf(gv, gv, fmaf(gh, gh, EPS)));
        sum += fabsf(a - b);

        // pixel j=2
        gv = di.z - ui.z; gh = ci.w - ci.y;
        a  = sqrtf(fmaf(gv, gv, fmaf(gh, gh, EPS)));
        gv = dt.z - ut.z; gh = ct.w - ct.y;
        b  = sqrtf(fmaf(gv, gv, fmaf(gh, gh, EPS)));
        sum += fabsf(a - b);

        // pixel j=3
        gv = di.w - ui.w; gh = rci - ci.z;
        a  = sqrtf(fmaf(gv, gv, fmaf(gh, gh, EPS)));
        gv = dt.w - ut.w; gh = rct - ct.z;
        b  = sqrtf(fmaf(gv, gv, fmaf(gh, gh, EPS)));
        sum += fabsf(a - b);

        // march
        ui = ci; ci = di;
        ut = ct; ct = dt;
    }

    // block reduction: warp shfl, then across 4 warps via smem
    #pragma unroll
    for (int o = 16; o > 0; o >>= 1)
        sum += __shfl_down_sync(0xffffffffu, sum, o);

    __shared__ float ws[TPB / 32];
    if ((t & 31) == 0) ws[t >> 5] = sum;
    __syncthreads();
    if (t == 0) {
        float s = 0.f;
        #pragma unroll
        for (int i = 0; i < TPB / 32; ++i) s += ws[i];
        g_partials[blockIdx.x] = s;
    }
}

__global__ __launch_bounds__(256)
void reduce_kernel(float* __restrict__ out, int nparts, float inv_n) {
    float s = 0.f;
    for (int i = threadIdx.x; i < nparts; i += 256)
        s += g_partials[i];

    #pragma unroll
    for (int o = 16; o > 0; o >>= 1)
        s += __shfl_down_sync(0xffffffffu, s, o);

    __shared__ float ws[8];
    int t = threadIdx.x;
    if ((t & 31) == 0) ws[t >> 5] = s;
    __syncthreads();
    if (t == 0) {
        float tot = 0.f;
        #pragma unroll
        for (int i = 0; i < 8; ++i) tot += ws[i];
        out[0] = tot * inv_n;
    }
}

extern "C" void kernel_launch(void* const* d_in, const int* in_sizes, int n_in,
                              void* d_out, int out_size) {
    const float* in = (const float*)d_in[0];
    const float* tg = (const float*)d_in[1];
    float* out = (float*)d_out;

    const int total  = in_sizes[0];               // 32*3*512*512
    const int planes = total / (HH * WW);         // 96
    const int blocks = planes * (HH / RPB);       // 1536

    grad_loss_kernel<<<blocks, TPB>>>(in, tg);
    reduce_kernel<<<1, 256>>>(out, blocks, 1.0f / (float)total);
}

// round 2
// speedup vs baseline: 1.2369x; 1.2369x over previous
#include <cuda_runtime.h>

#define HH 512
#define WW 512
#define RPB 32            // rows per block
#define TPB 128           // threads per block: 128 * 4 cols = 512 = WW
#define EPS 1e-6f

// scratch for per-block partial sums + completion ticket (no cudaMalloc allowed)
__device__ float g_partials[2048];
__device__ unsigned int g_ticket;   // zero-init; last block resets it to 0

__device__ __forceinline__ float4 ld4(const float* __restrict__ p) {
    return *reinterpret_cast<const float4*>(p);
}

// single-MUFU approximate sqrt (max rel err ~1e-7, far below 1e-3 tolerance)
__device__ __forceinline__ float fsqrt_ap(float x) {
    float r;
    asm("sqrt.approx.f32 %0, %1;" : "=f"(r) : "f"(x));
    return r;
}

__global__ __launch_bounds__(TPB)
void grad_loss_kernel(const float* __restrict__ in, const float* __restrict__ tg,
                      float* __restrict__ out, int nblocks, float inv_n) {
    const int t  = threadIdx.x;
    const int w0 = t * 4;
    const int bands_per_plane = HH / RPB;
    const int plane = blockIdx.x / bands_per_plane;
    const int band  = blockIdx.x % bands_per_plane;
    const int r0 = band * RPB;

    const float* __restrict__ bi = in + (size_t)plane * HH * WW;
    const float* __restrict__ bt = tg + (size_t)plane * HH * WW;

    float4 ui, ci, di, ut, ct, dt;
    const float4 z4 = make_float4(0.f, 0.f, 0.f, 0.f);

    if (r0 > 0) {
        ui = ld4(bi + (size_t)(r0 - 1) * WW + w0);
        ut = ld4(bt + (size_t)(r0 - 1) * WW + w0);
    } else {
        ui = z4; ut = z4;
    }
    ci = ld4(bi + (size_t)r0 * WW + w0);
    ct = ld4(bt + (size_t)r0 * WW + w0);

    float sum = 0.f;

    #pragma unroll 4
    for (int r = r0; r < r0 + RPB; ++r) {
        if (r + 1 < HH) {
            di = ld4(bi + (size_t)(r + 1) * WW + w0);
            dt = ld4(bt + (size_t)(r + 1) * WW + w0);
        } else {
            di = z4; dt = z4;
        }
        // horizontal neighbors at float4 boundaries (L1 hits)
        const float lci = (w0 > 0)      ? bi[(size_t)r * WW + w0 - 1] : 0.f;
        const float rci = (w0 + 4 < WW) ? bi[(size_t)r * WW + w0 + 4] : 0.f;
        const float lct = (w0 > 0)      ? bt[(size_t)r * WW + w0 - 1] : 0.f;
        const float rct = (w0 + 4 < WW) ? bt[(size_t)r * WW + w0 + 4] : 0.f;

        float gv, gh, a, b;

        gv = di.x - ui.x; gh = ci.y - lci;
        a  = fsqrt_ap(fmaf(gv, gv, fmaf(gh, gh, EPS)));
        gv = dt.x - ut.x; gh = ct.y - lct;
        b  = fsqrt_ap(fmaf(gv, gv, fmaf(gh, gh, EPS)));
        sum += fabsf(a - b);

        gv = di.y - ui.y; gh = ci.z - ci.x;
        a  = fsqrt_ap(fmaf(gv, gv, fmaf(gh, gh, EPS)));
        gv = dt.y - ut.y; gh = ct.z - ct.x;
        b  = fsqrt_ap(fmaf(gv, gv, fmaf(gh, gh, EPS)));
        sum += fabsf(a - b);

        gv = di.z - ui.z; gh = ci.w - ci.y;
        a  = fsqrt_ap(fmaf(gv, gv, fmaf(gh, gh, EPS)));
        gv = dt.z - ut.z; gh = ct.w - ct.y;
        b  = fsqrt_ap(fmaf(gv, gv, fmaf(gh, gh, EPS)));
        sum += fabsf(a - b);

        gv = di.w - ui.w; gh = rci - ci.z;
        a  = fsqrt_ap(fmaf(gv, gv, fmaf(gh, gh, EPS)));
        gv = dt.w - ut.w; gh = rct - ct.z;
        b  = fsqrt_ap(fmaf(gv, gv, fmaf(gh, gh, EPS)));
        sum += fabsf(a - b);

        ui = ci; ci = di;
        ut = ct; ct = dt;
    }

    // block reduction: warp shfl, then across 4 warps via smem
    #pragma unroll
    for (int o = 16; o > 0; o >>= 1)
        sum += __shfl_down_sync(0xffffffffu, sum, o);

    __shared__ float ws[TPB / 32];
    __shared__ bool is_last;
    if ((t & 31) == 0) ws[t >> 5] = sum;
    __syncthreads();

    if (t == 0) {
        float s = ws[0] + ws[1] + ws[2] + ws[3];
        g_partials[blockIdx.x] = s;
        __threadfence();                               // partial visible before ticket
        unsigned done = atomicAdd(&g_ticket, 1u);
        is_last = (done == (unsigned)(nblocks - 1));
    }
    __syncthreads();

    if (is_last) {
        // all partials are globally visible (each writer fenced before its ticket)
        const volatile float* vp = (const volatile float*)g_partials;
        float s = 0.f;
        for (int i = t; i < nblocks; i += TPB)
            s += vp[i];

        #pragma unroll
        for (int o = 16; o > 0; o >>= 1)
            s += __shfl_down_sync(0xffffffffu, s, o);

        if ((t & 31) == 0) ws[t >> 5] = s;
        __syncthreads();
        if (t == 0) {
            out[0] = (ws[0] + ws[1] + ws[2] + ws[3]) * inv_n;
            g_ticket = 0;                              // reset for next graph replay
        }
    }
}

extern "C" void kernel_launch(void* const* d_in, const int* in_sizes, int n_in,
                              void* d_out, int out_size) {
    const float* in = (const float*)d_in[0];
    const float* tg = (const float*)d_in[1];
    float* out = (float*)d_out;

    const int total  = in_sizes[0];               // 32*3*512*512
    const int planes = total / (HH * WW);         // 96
    const int blocks = planes * (HH / RPB);       // 1536

    grad_loss_kernel<<<blocks, TPB>>>(in, tg, out, blocks, 1.0f / (float)total);
}

// round 3
// speedup vs baseline: 1.4897x; 1.2044x over previous
#include <cuda_runtime.h>

#define HH 512
#define WW 512
#define RPB 16            // rows per block
#define TPB 128           // threads per block: 128 * 4 cols = 512 = WW
#define EPS 1e-6f

// scratch for per-block partial sums + completion ticket (no cudaMalloc allowed)
__device__ float g_partials[4096];
__device__ unsigned int g_ticket;   // zero-init; last block resets it to 0

__device__ __forceinline__ float4 ld4(const float* __restrict__ p) {
    return *reinterpret_cast<const float4*>(p);
}

// single-MUFU approximate sqrt (max rel err ~1e-7, far below 1e-3 tolerance)
__device__ __forceinline__ float fsqrt_ap(float x) {
    float r;
    asm("sqrt.approx.f32 %0, %1;" : "=f"(r) : "f"(x));
    return r;
}

__global__ __launch_bounds__(TPB, 12)   // cap at 40 regs -> 12 blocks/SM (75% occ)
void grad_loss_kernel(const float* __restrict__ in, const float* __restrict__ tg,
                      float* __restrict__ out, int nblocks, float inv_n) {
    const int t  = threadIdx.x;
    const int w0 = t * 4;
    const int r0 = blockIdx.x * RPB;          // band
    const int plane = blockIdx.y;             // channel-plane

    const float* __restrict__ bi = in + (size_t)plane * HH * WW;
    const float* __restrict__ bt = tg + (size_t)plane * HH * WW;

    float4 ui, ci, di, ut, ct, dt;
    const float4 z4 = make_float4(0.f, 0.f, 0.f, 0.f);

    if (r0 > 0) {
        ui = ld4(bi + (r0 - 1) * WW + w0);
        ut = ld4(bt + (r0 - 1) * WW + w0);
    } else {
        ui = z4; ut = z4;
    }
    ci = ld4(bi + r0 * WW + w0);
    ct = ld4(bt + r0 * WW + w0);

    float sum = 0.f;

    #pragma unroll 4
    for (int r = r0; r < r0 + RPB; ++r) {
        if (r + 1 < HH) {
            di = ld4(bi + (r + 1) * WW + w0);
            dt = ld4(bt + (r + 1) * WW + w0);
        } else {
            di = z4; dt = z4;
        }
        // horizontal neighbors at float4 boundaries (L1 hits)
        const float lci = (w0 > 0)      ? bi[r * WW + w0 - 1] : 0.f;
        const float rci = (w0 + 4 < WW) ? bi[r * WW + w0 + 4] : 0.f;
        const float lct = (w0 > 0)      ? bt[r * WW + w0 - 1] : 0.f;
        const float rct = (w0 + 4 < WW) ? bt[r * WW + w0 + 4] : 0.f;

        float gv, gh, a, b;

        gv = di.x - ui.x; gh = ci.y - lci;
        a  = fsqrt_ap(fmaf(gv, gv, fmaf(gh, gh, EPS)));
        gv = dt.x - ut.x; gh = ct.y - lct;
        b  = fsqrt_ap(fmaf(gv, gv, fmaf(gh, gh, EPS)));
        sum += fabsf(a - b);

        gv = di.y - ui.y; gh = ci.z - ci.x;
        a  = fsqrt_ap(fmaf(gv, gv, fmaf(gh, gh, EPS)));
        gv = dt.y - ut.y; gh = ct.z - ct.x;
        b  = fsqrt_ap(fmaf(gv, gv, fmaf(gh, gh, EPS)));
        sum += fabsf(a - b);

        gv = di.z - ui.z; gh = ci.w - ci.y;
        a  = fsqrt_ap(fmaf(gv, gv, fmaf(gh, gh, EPS)));
        gv = dt.z - ut.z; gh = ct.w - ct.y;
        b  = fsqrt_ap(fmaf(gv, gv, fmaf(gh, gh, EPS)));
        sum += fabsf(a - b);

        gv = di.w - ui.w; gh = rci - ci.z;
        a  = fsqrt_ap(fmaf(gv, gv, fmaf(gh, gh, EPS)));
        gv = dt.w - ut.w; gh = rct - ct.z;
        b  = fsqrt_ap(fmaf(gv, gv, fmaf(gh, gh, EPS)));
        sum += fabsf(a - b);

        ui = ci; ci = di;
        ut = ct; ct = dt;
    }

    // block reduction: warp shfl, then across 4 warps via smem
    #pragma unroll
    for (int o = 16; o > 0; o >>= 1)
        sum += __shfl_down_sync(0xffffffffu, sum, o);

    __shared__ float ws[TPB / 32];
    __shared__ bool is_last;
    if ((t & 31) == 0) ws[t >> 5] = sum;
    __syncthreads();

    if (t == 0) {
        float s = ws[0] + ws[1] + ws[2] + ws[3];
        g_partials[blockIdx.y * gridDim.x + blockIdx.x] = s;
        __threadfence();                               // partial visible before ticket
        unsigned done = atomicAdd(&g_ticket, 1u);
        is_last = (done == (unsigned)(nblocks - 1));
    }
    __syncthreads();

    if (is_last) {
        // all partials globally visible (each writer fenced before its ticket)
        const volatile float* vp = (const volatile float*)g_partials;
        float s = 0.f;
        for (int i = t; i < nblocks; i += TPB)
            s += vp[i];

        #pragma unroll
        for (int o = 16; o > 0; o >>= 1)
            s += __shfl_down_sync(0xffffffffu, s, o);

        if ((t & 31) == 0) ws[t >> 5] = s;
        __syncthreads();
        if (t == 0) {
            out[0] = (ws[0] + ws[1] + ws[2] + ws[3]) * inv_n;
            g_ticket = 0;                              // reset for next graph replay
        }
    }
}

extern "C" void kernel_launch(void* const* d_in, const int* in_sizes, int n_in,
                              void* d_out, int out_size) {
    const float* in = (const float*)d_in[0];
    const float* tg = (const float*)d_in[1];
    float* out = (float*)d_out;

    const int total  = in_sizes[0];               // 32*3*512*512
    const int planes = total / (HH * WW);         // 96
    dim3 grid(HH / RPB, planes);                  // (32, 96) = 3072 blocks
    const int nblocks = (HH / RPB) * planes;

    grad_loss_kernel<<<grid, TPB>>>(in, tg, out, nblocks, 1.0f / (float)total);
}

// round 4
// speedup vs baseline: 1.5571x; 1.0453x over previous
#include <cuda_runtime.h>

#define HH 512
#define WW 512
#define TPB 128           // 128 threads * 4 cols = 512 = WW
#define NBLK 1824         // 152 SMs * 12 blocks/SM (GB300)
#define EPS 1e-6f

// scratch for per-block partial sums + completion ticket (no cudaMalloc allowed)
__device__ float g_partials[NBLK];
__device__ unsigned int g_ticket;   // zero-init; last block resets it to 0

__device__ __forceinline__ float4 ld4(const float* __restrict__ p) {
    return *reinterpret_cast<const float4*>(p);
}

// single-MUFU approximate sqrt (max rel err ~1e-7, far below 1e-3 tolerance)
__device__ __forceinline__ float fsqrt_ap(float x) {
    float r;
    asm("sqrt.approx.f32 %0, %1;" : "=f"(r) : "f"(x));
    return r;
}

__global__ __launch_bounds__(TPB, 12)   // cap regs at 40 -> 12 blocks/SM
void grad_loss_kernel(const float* __restrict__ in, const float* __restrict__ tg,
                      float* __restrict__ out, int total_rows, float inv_n) {
    const int t  = threadIdx.x;
    const int w0 = t * 4;

    // even split of the flattened row space [0, total_rows)
    const int nb   = gridDim.x;
    const int base = total_rows / nb;
    const int rem  = total_rows % nb;
    const int bid  = blockIdx.x;
    const int rs   = bid * base + min(bid, rem);
    const int re   = rs + base + (bid < rem ? 1 : 0);

    // row pointers (bumped by WW per row); all loads use immediate offsets
    const float* __restrict__ pi = in + (size_t)rs * WW + w0;
    const float* __restrict__ pt = tg + (size_t)rs * WW + w0;

    const bool hasL = (w0 > 0);
    const bool hasR = (w0 + 4 < WW);

    float4 ui, ci, di, ut, ct, dt;
    const float4 z4 = make_float4(0.f, 0.f, 0.f, 0.f);

    // init marchers for row rs (if rs is a plane start, in-loop branch handles it)
    if ((rs & (HH - 1)) != 0) {
        ui = ld4(pi - WW); ut = ld4(pt - WW);
        ci = ld4(pi);      ct = ld4(pt);
    } else {
        ui = z4; ut = z4; ci = z4; ct = z4;   // overwritten by r==0 branch
    }

    float sum = 0.f;

    for (int rg = rs; rg < re; ++rg) {
        const int r = rg & (HH - 1);
        if (r == 0) {                          // plane start: reset marchers
            ui = z4; ut = z4;
            ci = ld4(pi); ct = ld4(pt);
        }
        if (r + 1 < HH) {
            di = ld4(pi + WW);
            dt = ld4(pt + WW);
        } else {
            di = z4; dt = z4;
        }
        // horizontal neighbors at float4 boundaries (immediate-offset L1 hits)
        const float lci = hasL ? pi[-1] : 0.f;
        const float rci = hasR ? pi[4]  : 0.f;
        const float lct = hasL ? pt[-1] : 0.f;
        const float rct = hasR ? pt[4]  : 0.f;

        float gv, gh, a, b;

        gv = di.x - ui.x; gh = ci.y - lci;
        a  = fsqrt_ap(fmaf(gv, gv, fmaf(gh, gh, EPS)));
        gv = dt.x - ut.x; gh = ct.y - lct;
        b  = fsqrt_ap(fmaf(gv, gv, fmaf(gh, gh, EPS)));
        sum += fabsf(a - b);

        gv = di.y - ui.y; gh = ci.z - ci.x;
        a  = fsqrt_ap(fmaf(gv, gv, fmaf(gh, gh, EPS)));
        gv = dt.y - ut.y; gh = ct.z - ct.x;
        b  = fsqrt_ap(fmaf(gv, gv, fmaf(gh, gh, EPS)));
        sum += fabsf(a - b);

        gv = di.z - ui.z; gh = ci.w - ci.y;
        a  = fsqrt_ap(fmaf(gv, gv, fmaf(gh, gh, EPS)));
        gv = dt.z - ut.z; gh = ct.w - ct.y;
        b  = fsqrt_ap(fmaf(gv, gv, fmaf(gh, gh, EPS)));
        sum += fabsf(a - b);

        gv = di.w - ui.w; gh = rci - ci.z;
        a  = fsqrt_ap(fmaf(gv, gv, fmaf(gh, gh, EPS)));
        gv = dt.w - ut.w; gh = rct - ct.z;
        b  = fsqrt_ap(fmaf(gv, gv, fmaf(gh, gh, EPS)));
        sum += fabsf(a - b);

        // march
        ui = ci; ci = di;
        ut = ct; ct = dt;
        pi += WW; pt += WW;
    }

    // block reduction: warp shfl, then across 4 warps via smem
    #pragma unroll
    for (int o = 16; o > 0; o >>= 1)
        sum += __shfl_down_sync(0xffffffffu, sum, o);

    __shared__ float ws[TPB / 32];
    __shared__ bool is_last;
    if ((t & 31) == 0) ws[t >> 5] = sum;
    __syncthreads();

    if (t == 0) {
        float s = ws[0] + ws[1] + ws[2] + ws[3];
        g_partials[bid] = s;
        __threadfence();                               // partial visible before ticket
        unsigned done = atomicAdd(&g_ticket, 1u);
        is_last = (done == (unsigned)(nb - 1));
    }
    __syncthreads();

    if (is_last) {
        const volatile float* vp = (const volatile float*)g_partials;
        float s = 0.f;
        for (int i = t; i < nb; i += TPB)
            s += vp[i];

        #pragma unroll
        for (int o = 16; o > 0; o >>= 1)
            s += __shfl_down_sync(0xffffffffu, s, o);

        if ((t & 31) == 0) ws[t >> 5] = s;
        __syncthreads();
        if (t == 0) {
            out[0] = (ws[0] + ws[1] + ws[2] + ws[3]) * inv_n;
            g_ticket = 0;                              // reset for next graph replay
        }
    }
}

extern "C" void kernel_launch(void* const* d_in, const int* in_sizes, int n_in,
                              void* d_out, int out_size) {
    const float* in = (const float*)d_in[0];
    const float* tg = (const float*)d_in[1];
    float* out = (float*)d_out;

    const int total = in_sizes[0];                 // 32*3*512*512
    const int total_rows = total / WW;             // 49152

    grad_loss_kernel<<<NBLK, TPB>>>(in, tg, out, total_rows, 1.0f / (float)total);
}

// round 5
// speedup vs baseline: 1.6097x; 1.0337x over previous
#include <cuda_runtime.h>

#define HH 512
#define WW 512
#define TPB 128           // 128 threads * 4 cols = 512 = WW
#define NBLK 1824         // 152 SMs * 12 blocks/SM (GB300)
#define EPS 1e-6f

// scratch for per-block partial sums + completion ticket (no cudaMalloc allowed)
__device__ float g_partials[NBLK];
__device__ unsigned int g_ticket;   // zero-init; last block resets it to 0

__device__ __forceinline__ float4 ld4(const float* __restrict__ p) {
    return *reinterpret_cast<const float4*>(p);
}

// single-MUFU approximate sqrt (max rel err ~1e-7, far below 1e-3 tolerance)
__device__ __forceinline__ float fsqrt_ap(float x) {
    float r;
    asm("sqrt.approx.f32 %0, %1;" : "=f"(r) : "f"(x));
    return r;
}

__global__ __launch_bounds__(TPB, 12)   // cap regs at 40 -> 12 blocks/SM
void grad_loss_kernel(const float* __restrict__ in, const float* __restrict__ tg,
                      float* __restrict__ out, int total_rows, float inv_n) {
    const int t    = threadIdx.x;
    const int lane = t & 31;
    const int w0   = t * 4;
    const bool hasL = (w0 > 0);
    const bool hasR = (w0 + 4 < WW);

    // even split of the flattened row space [0, total_rows)
    const int nb   = gridDim.x;
    const int base = total_rows / nb;
    const int rem  = total_rows % nb;
    const int bid  = blockIdx.x;
    const int rs   = bid * base + min(bid, rem);
    const int re   = rs + base + (bid < rem ? 1 : 0);

    const float* pi = in + (size_t)rs * WW + w0;
    const float* pt = tg + (size_t)rs * WW + w0;

    const float4 z4 = make_float4(0.f, 0.f, 0.f, 0.f);
    float sum = 0.f;

    // 3 rotating slots per array: roles (up, cur, next)
    float4 Xi, Yi, Zi, Xt, Yt, Zt;

    if ((rs & (HH - 1)) != 0) {
        Xi = ld4(pi - WW); Xt = ld4(pt - WW);
        Yi = ld4(pi);      Yt = ld4(pt);
    } else {
        Xi = z4; Xt = z4; Yi = z4; Yt = z4;   // step's r==0 branch reloads cur
    }

    // one row step: u/c resident, loads next row into n, rotates via call-site
    auto step = [&](float4& u_i, float4& c_i, float4& n_i,
                    float4& u_t, float4& c_t, float4& n_t, int rg) {
        const int r = rg & (HH - 1);
        if (r == 0) {                          // plane start
            u_i = z4; u_t = z4;
            c_i = ld4(pi); c_t = ld4(pt);
        }
        if (r + 1 < HH) {
            n_i = ld4(pi + WW); n_t = ld4(pt + WW);
        } else {
            n_i = z4; n_t = z4;
        }

        // horizontal neighbors via warp shuffle; warp-edge lanes fall back to
        // a single-lane predicated load (1 wavefront instead of 16)
        float lci = __shfl_up_sync(0xffffffffu, c_i.w, 1);
        float lct = __shfl_up_sync(0xffffffffu, c_t.w, 1);
        float rci = __shfl_down_sync(0xffffffffu, c_i.x, 1);
        float rct = __shfl_down_sync(0xffffffffu, c_t.x, 1);
        if (lane == 0)  { lci = hasL ? pi[-1] : 0.f; lct = hasL ? pt[-1] : 0.f; }
        if (lane == 31) { rci = hasR ? pi[4]  : 0.f; rct = hasR ? pt[4]  : 0.f; }

        float gv, gh, a, b;

        gv = n_i.x - u_i.x; gh = c_i.y - lci;
        a  = fsqrt_ap(fmaf(gv, gv, fmaf(gh, gh, EPS)));
        gv = n_t.x - u_t.x; gh = c_t.y - lct;
        b  = fsqrt_ap(fmaf(gv, gv, fmaf(gh, gh, EPS)));
        sum += fabsf(a - b);

        gv = n_i.y - u_i.y; gh = c_i.z - c_i.x;
        a  = fsqrt_ap(fmaf(gv, gv, fmaf(gh, gh, EPS)));
        gv = n_t.y - u_t.y; gh = c_t.z - c_t.x;
        b  = fsqrt_ap(fmaf(gv, gv, fmaf(gh, gh, EPS)));
        sum += fabsf(a - b);

        gv = n_i.z - u_i.z; gh = c_i.w - c_i.y;
        a  = fsqrt_ap(fmaf(gv, gv, fmaf(gh, gh, EPS)));
        gv = n_t.z - u_t.z; gh = c_t.w - c_t.y;
        b  = fsqrt_ap(fmaf(gv, gv, fmaf(gh, gh, EPS)));
        sum += fabsf(a - b);

        gv = n_i.w - u_i.w; gh = rci - c_i.z;
        a  = fsqrt_ap(fmaf(gv, gv, fmaf(gh, gh, EPS)));
        gv = n_t.w - u_t.w; gh = rct - c_t.z;
        b  = fsqrt_ap(fmaf(gv, gv, fmaf(gh, gh, EPS)));
        sum += fabsf(a - b);

        pi += WW; pt += WW;
    };

    int rg = rs;
    // unrolled x3 with explicit register rotation (no u=c; c=d MOV chains)
    for (; rg + 3 <= re; rg += 3) {
        step(Xi, Yi, Zi, Xt, Yt, Zt, rg);
        step(Yi, Zi, Xi, Yt, Zt, Xt, rg + 1);
        step(Zi, Xi, Yi, Zt, Xt, Yt, rg + 2);
    }
    if (rg < re) {
        step(Xi, Yi, Zi, Xt, Yt, Zt, rg);
        ++rg;
        if (rg < re)
            step(Yi, Zi, Xi, Yt, Zt, Xt, rg);
    }

    // block reduction: warp shfl, then across 4 warps via smem
    #pragma unroll
    for (int o = 16; o > 0; o >>= 1)
        sum += __shfl_down_sync(0xffffffffu, sum, o);

    __shared__ float ws[TPB / 32];
    __shared__ bool is_last;
    if ((t & 31) == 0) ws[t >> 5] = sum;
    __syncthreads();

    if (t == 0) {
        float s = ws[0] + ws[1] + ws[2] + ws[3];
        g_partials[bid] = s;
        __threadfence();                               // partial visible before ticket
        unsigned done = atomicAdd(&g_ticket, 1u);
        is_last = (done == (unsigned)(nb - 1));
    }
    __syncthreads();

    if (is_last) {
        const volatile float* vp = (const volatile float*)g_partials;
        float s = 0.f;
        for (int i = t; i < nb; i += TPB)
            s += vp[i];

        #pragma unroll
        for (int o = 16; o > 0; o >>= 1)
            s += __shfl_down_sync(0xffffffffu, s, o);

        if ((t & 31) == 0) ws[t >> 5] = s;
        __syncthreads();
        if (t == 0) {
            out[0] = (ws[0] + ws[1] + ws[2] + ws[3]) * inv_n;
            g_ticket = 0;                              // reset for next graph replay
        }
    }
}

extern "C" void kernel_launch(void* const* d_in, const int* in_sizes, int n_in,
                              void* d_out, int out_size) {
    const float* in = (const float*)d_in[0];
    const float* tg = (const float*)d_in[1];
    float* out = (float*)d_out;

    const int total = in_sizes[0];                 // 32*3*512*512
    const int total_rows = total / WW;             // 49152

    grad_loss_kernel<<<NBLK, TPB>>>(in, tg, out, total_rows, 1.0f / (float)total);
}